// round 2
// baseline (speedup 1.0000x reference)
#include <cuda_runtime.h>

#define IMG_H 200
#define IMG_W 200
#define VOLD 256

__device__ __forceinline__ float fetch_checked(const float* __restrict__ vol,
                                               int i, int j, int k) {
    if ((unsigned)i < (unsigned)VOLD && (unsigned)j < (unsigned)VOLD &&
        (unsigned)k < (unsigned)VOLD)
        return __ldg(vol + ((i * VOLD + j) * VOLD + k));
    return 0.0f;
}

// Load pair (v[iz], v[iz+1]) from one volume row using a single aligned
// LDG.128 plus a rarely-active predicated scalar load. rowbase points at
// the start offset (ix*VOLD+iy)*VOLD; 0 <= iz <= VOLD-2 guaranteed.
__device__ __forceinline__ void load_zpair(const float* __restrict__ row,
                                           int iz, float& a, float& b) {
    const int iz0 = iz & ~3;
    const int m   = iz & 3;
    const float4 q = __ldg((const float4*)(row + iz0));
    float ext = 0.0f;
    if (m == 3) ext = __ldg(row + iz0 + 4);
    a = (m == 0) ? q.x : (m == 1) ? q.y : (m == 2) ? q.z : q.w;
    b = (m == 0) ? q.y : (m == 1) ? q.z : (m == 2) ? q.w : ext;
}

__global__ void __launch_bounds__(256) drr_kernel(
    const float* __restrict__ volume,
    const float* __restrict__ k_inv,     // (1,3,3)
    const float* __restrict__ rt_inv,    // (1,4,4)
    const float* __restrict__ sdd_p,     // (1,)
    const float* __restrict__ affine_inv,// (4,4)
    const int*   __restrict__ n_samples_p,
    float* __restrict__ out)
{
    const int gwarp = (blockIdx.x * blockDim.x + threadIdx.x) >> 5;
    const int lane  = threadIdx.x & 31;
    if (gwarp >= IMG_H * IMG_W) return;

    const int u = gwarp % IMG_W;   // x (col)
    const int v = gwarp / IMG_W;   // y (row)

    const int   n   = *n_samples_p;
    const float sdd = *sdd_p;
    const float inv_nm1 = 1.0f / (float)(n - 1);

    const float px = (float)u, py = (float)v;

    // tgt_cam = k_inv @ [u,v,1] * sdd
    const float tc0 = (k_inv[0] * px + k_inv[1] * py + k_inv[2]) * sdd;
    const float tc1 = (k_inv[3] * px + k_inv[4] * py + k_inv[5]) * sdd;
    const float tc2 = (k_inv[6] * px + k_inv[7] * py + k_inv[8]) * sdd;

    // rt_inv (4x4 row-major): R = [:3,:3], t = [:3,3]
    const float r00 = rt_inv[0],  r01 = rt_inv[1],  r02 = rt_inv[2],  t0 = rt_inv[3];
    const float r10 = rt_inv[4],  r11 = rt_inv[5],  r12 = rt_inv[6],  t1 = rt_inv[7];
    const float r20 = rt_inv[8],  r21 = rt_inv[9],  r22 = rt_inv[10], t2 = rt_inv[11];

    const float ray0 = r00 * tc0 + r01 * tc1 + r02 * tc2;
    const float ray1 = r10 * tc0 + r11 * tc1 + r12 * tc2;
    const float ray2 = r20 * tc0 + r21 * tc1 + r22 * tc2;

    const float a00 = affine_inv[0],  a01 = affine_inv[1],  a02 = affine_inv[2],  b0 = affine_inv[3];
    const float a10 = affine_inv[4],  a11 = affine_inv[5],  a12 = affine_inv[6],  b1 = affine_inv[7];
    const float a20 = affine_inv[8],  a21 = affine_inv[9],  a22 = affine_inv[10], b2 = affine_inv[11];

    // vox(t) = p0 + t * d   (t in [0,1])
    const float p0x = a00 * t0 + a01 * t1 + a02 * t2 + b0;
    const float p0y = a10 * t0 + a11 * t1 + a12 * t2 + b1;
    const float p0z = a20 * t0 + a21 * t1 + a22 * t2 + b2;
    const float dx  = a00 * ray0 + a01 * ray1 + a02 * ray2;
    const float dy  = a10 * ray0 + a11 * ray1 + a12 * ray2;
    const float dz  = a20 * ray0 + a21 * ray1 + a22 * ray2;

    // Parametric AABB clip vs open interval (-1, VOLD); outside samples are
    // exactly 0 (mode='constant'). 1-sample margin; per-corner checks keep
    // boundary samples exact.
    float tlo = 0.0f, thi = 1.0f;
    {
        const float P[3] = {p0x, p0y, p0z};
        const float D[3] = {dx, dy, dz};
        #pragma unroll
        for (int a = 0; a < 3; ++a) {
            if (fabsf(D[a]) > 1e-12f) {
                const float inv = 1.0f / D[a];
                const float ta = (-1.0f - P[a]) * inv;
                const float tb = ((float)VOLD - P[a]) * inv;
                tlo = fmaxf(tlo, fminf(ta, tb));
                thi = fminf(thi, fmaxf(ta, tb));
            } else if (P[a] <= -1.0f || P[a] >= (float)VOLD) {
                thi = -1.0f;  // empty
            }
        }
    }
    int smin = (int)floorf(tlo * (float)(n - 1)) - 1;
    int smax = (int)ceilf (thi * (float)(n - 1)) + 1;
    if (smin < 0)     smin = 0;
    if (smax > n - 1) smax = n - 1;

    float sum = 0.0f;
    for (int s = smin + lane; s <= smax; s += 32) {
        const float t = (float)s * inv_nm1;
        const float x = fmaf(t, dx, p0x);
        const float y = fmaf(t, dy, p0y);
        const float z = fmaf(t, dz, p0z);

        const float flx = floorf(x), fly = floorf(y), flz = floorf(z);
        const int ix = (int)flx, iy = (int)fly, iz = (int)flz;
        const float wx = x - flx, wy = y - fly, wz = z - flz;

        float v000, v001, v010, v011, v100, v101, v110, v111;
        if ((unsigned)ix < (unsigned)(VOLD - 1) &&
            (unsigned)iy < (unsigned)(VOLD - 1) &&
            (unsigned)iz < (unsigned)(VOLD - 1)) {
            // interior: 4 z-pair loads via aligned LDG.128
            const float* row00 = volume + ((ix * VOLD + iy) * VOLD);
            load_zpair(row00,                       iz, v000, v001);
            load_zpair(row00 + VOLD,                iz, v010, v011);
            load_zpair(row00 + VOLD * VOLD,         iz, v100, v101);
            load_zpair(row00 + VOLD * VOLD + VOLD,  iz, v110, v111);
        } else {
            v000 = fetch_checked(volume, ix,     iy,     iz);
            v001 = fetch_checked(volume, ix,     iy,     iz + 1);
            v010 = fetch_checked(volume, ix,     iy + 1, iz);
            v011 = fetch_checked(volume, ix,     iy + 1, iz + 1);
            v100 = fetch_checked(volume, ix + 1, iy,     iz);
            v101 = fetch_checked(volume, ix + 1, iy,     iz + 1);
            v110 = fetch_checked(volume, ix + 1, iy + 1, iz);
            v111 = fetch_checked(volume, ix + 1, iy + 1, iz + 1);
        }

        const float c00 = fmaf(wz, v001 - v000, v000);
        const float c01 = fmaf(wz, v011 - v010, v010);
        const float c10 = fmaf(wz, v101 - v100, v100);
        const float c11 = fmaf(wz, v111 - v110, v110);
        const float c0  = fmaf(wy, c01 - c00, c00);
        const float c1  = fmaf(wy, c11 - c10, c10);
        sum += fmaf(wx, c1 - c0, c0);
    }

    #pragma unroll
    for (int o = 16; o > 0; o >>= 1)
        sum += __shfl_xor_sync(0xFFFFFFFFu, sum, o);

    if (lane == 0) {
        const float raylen = sqrtf(ray0 * ray0 + ray1 * ray1 + ray2 * ray2);
        out[gwarp] = sum * raylen * inv_nm1;
    }
}

extern "C" void kernel_launch(void* const* d_in, const int* in_sizes, int n_in,
                              void* d_out, int out_size) {
    const float* volume     = (const float*)d_in[0];
    const float* k_inv      = (const float*)d_in[1];
    const float* rt_inv     = (const float*)d_in[2];
    const float* sdd        = (const float*)d_in[3];
    const float* affine_inv = (const float*)d_in[4];
    const int*   n_samples  = (const int*)  d_in[5];
    float* out = (float*)d_out;

    const int total_threads = IMG_H * IMG_W * 32;  // one warp per pixel
    const int block = 256;
    const int grid  = (total_threads + block - 1) / block;
    drr_kernel<<<grid, block>>>(volume, k_inv, rt_inv, sdd, affine_inv,
                                n_samples, out);
}

// round 3
// speedup vs baseline: 1.4027x; 1.4027x over previous
#include <cuda_runtime.h>

#define IMG_H 200
#define IMG_W 200
#define VOLD 256

__device__ __forceinline__ float fetch_checked(const float* __restrict__ vol,
                                               int i, int j, int k) {
    if ((unsigned)i < (unsigned)VOLD && (unsigned)j < (unsigned)VOLD &&
        (unsigned)k < (unsigned)VOLD)
        return __ldg(vol + ((i * VOLD + j) * VOLD + k));
    return 0.0f;
}

// Pair (v[iz], v[iz+1]) via one aligned LDG.64 + predicated scalar fix-up.
// row points at start of the volume row; interior guarantees 0 <= iz <= 254.
__device__ __forceinline__ void load_zpair64(const float* __restrict__ row,
                                             int iz0, bool odd,
                                             float& a, float& b) {
    const float2 q = __ldg((const float2*)(row + iz0));
    float ext = 0.0f;
    if (odd) ext = __ldg(row + iz0 + 2);
    a = odd ? q.y : q.x;
    b = odd ? ext : q.y;
}

__global__ void __launch_bounds__(256) drr_kernel(
    const float* __restrict__ volume,
    const float* __restrict__ k_inv,     // (1,3,3)
    const float* __restrict__ rt_inv,    // (1,4,4)
    const float* __restrict__ sdd_p,     // (1,)
    const float* __restrict__ affine_inv,// (4,4)
    const int*   __restrict__ n_samples_p,
    float* __restrict__ out)
{
    const int gwarp = (blockIdx.x * blockDim.x + threadIdx.x) >> 5;
    const int lane  = threadIdx.x & 31;
    if (gwarp >= IMG_H * IMG_W) return;

    const int u = gwarp % IMG_W;   // x (col)
    const int v = gwarp / IMG_W;   // y (row)

    const int   n   = *n_samples_p;
    const float sdd = *sdd_p;
    const float inv_nm1 = 1.0f / (float)(n - 1);

    const float px = (float)u, py = (float)v;

    // tgt_cam = k_inv @ [u,v,1] * sdd
    const float tc0 = (k_inv[0] * px + k_inv[1] * py + k_inv[2]) * sdd;
    const float tc1 = (k_inv[3] * px + k_inv[4] * py + k_inv[5]) * sdd;
    const float tc2 = (k_inv[6] * px + k_inv[7] * py + k_inv[8]) * sdd;

    // rt_inv (4x4 row-major): R = [:3,:3], t = [:3,3]
    const float r00 = rt_inv[0],  r01 = rt_inv[1],  r02 = rt_inv[2],  t0 = rt_inv[3];
    const float r10 = rt_inv[4],  r11 = rt_inv[5],  r12 = rt_inv[6],  t1 = rt_inv[7];
    const float r20 = rt_inv[8],  r21 = rt_inv[9],  r22 = rt_inv[10], t2 = rt_inv[11];

    const float ray0 = r00 * tc0 + r01 * tc1 + r02 * tc2;
    const float ray1 = r10 * tc0 + r11 * tc1 + r12 * tc2;
    const float ray2 = r20 * tc0 + r21 * tc1 + r22 * tc2;

    const float a00 = affine_inv[0],  a01 = affine_inv[1],  a02 = affine_inv[2],  b0 = affine_inv[3];
    const float a10 = affine_inv[4],  a11 = affine_inv[5],  a12 = affine_inv[6],  b1 = affine_inv[7];
    const float a20 = affine_inv[8],  a21 = affine_inv[9],  a22 = affine_inv[10], b2 = affine_inv[11];

    // vox(t) = p0 + t * d   (t in [0,1])
    const float p0x = a00 * t0 + a01 * t1 + a02 * t2 + b0;
    const float p0y = a10 * t0 + a11 * t1 + a12 * t2 + b1;
    const float p0z = a20 * t0 + a21 * t1 + a22 * t2 + b2;
    const float dx  = a00 * ray0 + a01 * ray1 + a02 * ray2;
    const float dy  = a10 * ray0 + a11 * ray1 + a12 * ray2;
    const float dz  = a20 * ray0 + a21 * ray1 + a22 * ray2;

    // Parametric AABB clip vs open interval (-1, VOLD); outside samples are
    // exactly 0 (mode='constant'). 1-sample margin; per-corner checks keep
    // boundary samples exact.
    float tlo = 0.0f, thi = 1.0f;
    {
        const float P[3] = {p0x, p0y, p0z};
        const float D[3] = {dx, dy, dz};
        #pragma unroll
        for (int a = 0; a < 3; ++a) {
            if (fabsf(D[a]) > 1e-12f) {
                const float inv = 1.0f / D[a];
                const float ta = (-1.0f - P[a]) * inv;
                const float tb = ((float)VOLD - P[a]) * inv;
                tlo = fmaxf(tlo, fminf(ta, tb));
                thi = fminf(thi, fmaxf(ta, tb));
            } else if (P[a] <= -1.0f || P[a] >= (float)VOLD) {
                thi = -1.0f;  // empty
            }
        }
    }
    int smin = (int)floorf(tlo * (float)(n - 1)) - 1;
    int smax = (int)ceilf (thi * (float)(n - 1)) + 1;
    if (smin < 0)     smin = 0;
    if (smax > n - 1) smax = n - 1;

    float sum = 0.0f;
    for (int s = smin + lane; s <= smax; s += 32) {
        const float t = (float)s * inv_nm1;
        const float x = fmaf(t, dx, p0x);
        const float y = fmaf(t, dy, p0y);
        const float z = fmaf(t, dz, p0z);

        const float flx = floorf(x), fly = floorf(y), flz = floorf(z);
        const int ix = (int)flx, iy = (int)fly, iz = (int)flz;
        const float wx = x - flx, wy = y - fly, wz = z - flz;

        float v000, v001, v010, v011, v100, v101, v110, v111;
        if ((unsigned)ix < (unsigned)(VOLD - 1) &&
            (unsigned)iy < (unsigned)(VOLD - 1) &&
            (unsigned)iz < (unsigned)(VOLD - 1)) {
            // interior: 4 z-pairs via aligned LDG.64 + predicated fix-up
            const int  iz0 = iz & ~1;
            const bool odd = (iz & 1) != 0;
            const float* row00 = volume + ((ix * VOLD + iy) * VOLD);
            load_zpair64(row00,                      iz0, odd, v000, v001);
            load_zpair64(row00 + VOLD,               iz0, odd, v010, v011);
            load_zpair64(row00 + VOLD * VOLD,        iz0, odd, v100, v101);
            load_zpair64(row00 + VOLD * VOLD + VOLD, iz0, odd, v110, v111);
        } else {
            v000 = fetch_checked(volume, ix,     iy,     iz);
            v001 = fetch_checked(volume, ix,     iy,     iz + 1);
            v010 = fetch_checked(volume, ix,     iy + 1, iz);
            v011 = fetch_checked(volume, ix,     iy + 1, iz + 1);
            v100 = fetch_checked(volume, ix + 1, iy,     iz);
            v101 = fetch_checked(volume, ix + 1, iy,     iz + 1);
            v110 = fetch_checked(volume, ix + 1, iy + 1, iz);
            v111 = fetch_checked(volume, ix + 1, iy + 1, iz + 1);
        }

        const float c00 = fmaf(wz, v001 - v000, v000);
        const float c01 = fmaf(wz, v011 - v010, v010);
        const float c10 = fmaf(wz, v101 - v100, v100);
        const float c11 = fmaf(wz, v111 - v110, v110);
        const float c0  = fmaf(wy, c01 - c00, c00);
        const float c1  = fmaf(wy, c11 - c10, c10);
        sum += fmaf(wx, c1 - c0, c0);
    }

    #pragma unroll
    for (int o = 16; o > 0; o >>= 1)
        sum += __shfl_xor_sync(0xFFFFFFFFu, sum, o);

    if (lane == 0) {
        const float raylen = sqrtf(ray0 * ray0 + ray1 * ray1 + ray2 * ray2);
        out[gwarp] = sum * raylen * inv_nm1;
    }
}

extern "C" void kernel_launch(void* const* d_in, const int* in_sizes, int n_in,
                              void* d_out, int out_size) {
    const float* volume     = (const float*)d_in[0];
    const float* k_inv      = (const float*)d_in[1];
    const float* rt_inv     = (const float*)d_in[2];
    const float* sdd        = (const float*)d_in[3];
    const float* affine_inv = (const float*)d_in[4];
    const int*   n_samples  = (const int*)  d_in[5];
    float* out = (float*)d_out;

    const int total_threads = IMG_H * IMG_W * 32;  // one warp per pixel
    const int block = 256;
    const int grid  = (total_threads + block - 1) / block;
    drr_kernel<<<grid, block>>>(volume, k_inv, rt_inv, sdd, affine_inv,
                                n_samples, out);
}

// round 4
// speedup vs baseline: 1.6025x; 1.1424x over previous
#include <cuda_runtime.h>

#define IMG_H 200
#define IMG_W 200
#define VOLD 256
#define NPIX (IMG_H * IMG_W)

// Per-pixel ray parameters (SoA), filled by precompute kernel each call.
__device__ float4 g_par0[NPIX];   // {p0x, p0y, p0z, ddx}
__device__ float4 g_par1[NPIX];   // {ddy, ddz, scale, bitcast(smin | smax<<16)}

__global__ void __launch_bounds__(256) precompute_kernel(
    const float* __restrict__ k_inv,     // (1,3,3)
    const float* __restrict__ rt_inv,    // (1,4,4)
    const float* __restrict__ sdd_p,     // (1,)
    const float* __restrict__ affine_inv,// (4,4)
    const int*   __restrict__ n_samples_p)
{
    const int pix = blockIdx.x * blockDim.x + threadIdx.x;
    if (pix >= NPIX) return;
    const int u = pix % IMG_W;
    const int v = pix / IMG_W;

    const int   n   = *n_samples_p;
    const float sdd = *sdd_p;
    const float inv_nm1 = 1.0f / (float)(n - 1);
    const float px = (float)u, py = (float)v;

    const float tc0 = (k_inv[0] * px + k_inv[1] * py + k_inv[2]) * sdd;
    const float tc1 = (k_inv[3] * px + k_inv[4] * py + k_inv[5]) * sdd;
    const float tc2 = (k_inv[6] * px + k_inv[7] * py + k_inv[8]) * sdd;

    const float r00 = rt_inv[0],  r01 = rt_inv[1],  r02 = rt_inv[2],  t0 = rt_inv[3];
    const float r10 = rt_inv[4],  r11 = rt_inv[5],  r12 = rt_inv[6],  t1 = rt_inv[7];
    const float r20 = rt_inv[8],  r21 = rt_inv[9],  r22 = rt_inv[10], t2 = rt_inv[11];

    const float ray0 = r00 * tc0 + r01 * tc1 + r02 * tc2;
    const float ray1 = r10 * tc0 + r11 * tc1 + r12 * tc2;
    const float ray2 = r20 * tc0 + r21 * tc1 + r22 * tc2;

    const float a00 = affine_inv[0],  a01 = affine_inv[1],  a02 = affine_inv[2],  b0 = affine_inv[3];
    const float a10 = affine_inv[4],  a11 = affine_inv[5],  a12 = affine_inv[6],  b1 = affine_inv[7];
    const float a20 = affine_inv[8],  a21 = affine_inv[9],  a22 = affine_inv[10], b2 = affine_inv[11];

    const float p0x = a00 * t0 + a01 * t1 + a02 * t2 + b0;
    const float p0y = a10 * t0 + a11 * t1 + a12 * t2 + b1;
    const float p0z = a20 * t0 + a21 * t1 + a22 * t2 + b2;
    const float dx  = a00 * ray0 + a01 * ray1 + a02 * ray2;
    const float dy  = a10 * ray0 + a11 * ray1 + a12 * ray2;
    const float dz  = a20 * ray0 + a21 * ray1 + a22 * ray2;

    // Parametric AABB clip vs open interval (-1, VOLD); outside samples are 0.
    float tlo = 0.0f, thi = 1.0f;
    {
        const float P[3] = {p0x, p0y, p0z};
        const float D[3] = {dx, dy, dz};
        #pragma unroll
        for (int a = 0; a < 3; ++a) {
            if (fabsf(D[a]) > 1e-12f) {
                const float inv = 1.0f / D[a];
                const float ta = (-1.0f - P[a]) * inv;
                const float tb = ((float)VOLD - P[a]) * inv;
                tlo = fmaxf(tlo, fminf(ta, tb));
                thi = fminf(thi, fmaxf(ta, tb));
            } else if (P[a] <= -1.0f || P[a] >= (float)VOLD) {
                thi = -1.0f;  // empty
            }
        }
    }
    int smin = (int)floorf(tlo * (float)(n - 1)) - 1;
    int smax = (int)ceilf (thi * (float)(n - 1)) + 1;
    if (smin < 0)     smin = 0;
    if (smax > n - 1) smax = n - 1;
    if (smax < smin) { smin = 1; smax = 0; }   // empty, keep pack non-negative

    const float raylen = sqrtf(ray0 * ray0 + ray1 * ray1 + ray2 * ray2);
    const float scale  = raylen * inv_nm1;

    // Fold inv_nm1 into direction: pos(s) = p0 + s * dd
    g_par0[pix] = make_float4(p0x, p0y, p0z, dx * inv_nm1);
    g_par1[pix] = make_float4(dy * inv_nm1, dz * inv_nm1, scale,
                              __int_as_float(smin | (smax << 16)));
}

__device__ __forceinline__ float fetch_checked(const float* __restrict__ vol,
                                               int i, int j, int k) {
    if ((unsigned)i < (unsigned)VOLD && (unsigned)j < (unsigned)VOLD &&
        (unsigned)k < (unsigned)VOLD)
        return __ldg(vol + ((i * VOLD + j) * VOLD + k));
    return 0.0f;
}

// Pair (v[iz], v[iz+1]) via one aligned LDG.64 + predicated scalar fix-up.
__device__ __forceinline__ void load_zpair64(const float* __restrict__ row,
                                             int iz0, bool odd,
                                             float& a, float& b) {
    const float2 q = __ldg((const float2*)(row + iz0));
    float ext = 0.0f;
    if (odd) ext = __ldg(row + iz0 + 2);
    a = odd ? q.y : q.x;
    b = odd ? ext : q.y;
}

__global__ void __launch_bounds__(256) drr_kernel(
    const float* __restrict__ volume,
    float* __restrict__ out)
{
    const int gwarp = (blockIdx.x * blockDim.x + threadIdx.x) >> 5;
    const int lane  = threadIdx.x & 31;
    if (gwarp >= NPIX) return;

    // Broadcast loads of precomputed per-pixel params.
    const float4 P0 = __ldg(&g_par0[gwarp]);
    const float4 P1 = __ldg(&g_par1[gwarp]);
    const float p0x = P0.x, p0y = P0.y, p0z = P0.z, ddx = P0.w;
    const float ddy = P1.x, ddz = P1.y, scale = P1.z;
    const int   pack = __float_as_int(P1.w);
    const int   smin = pack & 0xFFFF;
    const int   smax = pack >> 16;

    float sum = 0.0f;
    #pragma unroll 2
    for (int s = smin + lane; s <= smax; s += 32) {
        const float fs = (float)s;
        const float x = fmaf(fs, ddx, p0x);
        const float y = fmaf(fs, ddy, p0y);
        const float z = fmaf(fs, ddz, p0z);

        const float flx = floorf(x), fly = floorf(y), flz = floorf(z);
        const int ix = (int)flx, iy = (int)fly, iz = (int)flz;
        const float wx = x - flx, wy = y - fly, wz = z - flz;

        float v000, v001, v010, v011, v100, v101, v110, v111;
        if ((unsigned)ix < (unsigned)(VOLD - 1) &&
            (unsigned)iy < (unsigned)(VOLD - 1) &&
            (unsigned)iz < (unsigned)(VOLD - 1)) {
            const int  iz0 = iz & ~1;
            const bool odd = (iz & 1) != 0;
            const float* row00 = volume + ((ix * VOLD + iy) * VOLD);
            load_zpair64(row00,                      iz0, odd, v000, v001);
            load_zpair64(row00 + VOLD,               iz0, odd, v010, v011);
            load_zpair64(row00 + VOLD * VOLD,        iz0, odd, v100, v101);
            load_zpair64(row00 + VOLD * VOLD + VOLD, iz0, odd, v110, v111);
        } else {
            v000 = fetch_checked(volume, ix,     iy,     iz);
            v001 = fetch_checked(volume, ix,     iy,     iz + 1);
            v010 = fetch_checked(volume, ix,     iy + 1, iz);
            v011 = fetch_checked(volume, ix,     iy + 1, iz + 1);
            v100 = fetch_checked(volume, ix + 1, iy,     iz);
            v101 = fetch_checked(volume, ix + 1, iy,     iz + 1);
            v110 = fetch_checked(volume, ix + 1, iy + 1, iz);
            v111 = fetch_checked(volume, ix + 1, iy + 1, iz + 1);
        }

        const float c00 = fmaf(wz, v001 - v000, v000);
        const float c01 = fmaf(wz, v011 - v010, v010);
        const float c10 = fmaf(wz, v101 - v100, v100);
        const float c11 = fmaf(wz, v111 - v110, v110);
        const float c0  = fmaf(wy, c01 - c00, c00);
        const float c1  = fmaf(wy, c11 - c10, c10);
        sum += fmaf(wx, c1 - c0, c0);
    }

    #pragma unroll
    for (int o = 16; o > 0; o >>= 1)
        sum += __shfl_xor_sync(0xFFFFFFFFu, sum, o);

    if (lane == 0)
        out[gwarp] = sum * scale;
}

extern "C" void kernel_launch(void* const* d_in, const int* in_sizes, int n_in,
                              void* d_out, int out_size) {
    const float* volume     = (const float*)d_in[0];
    const float* k_inv      = (const float*)d_in[1];
    const float* rt_inv     = (const float*)d_in[2];
    const float* sdd        = (const float*)d_in[3];
    const float* affine_inv = (const float*)d_in[4];
    const int*   n_samples  = (const int*)  d_in[5];
    float* out = (float*)d_out;

    precompute_kernel<<<(NPIX + 255) / 256, 256>>>(k_inv, rt_inv, sdd,
                                                   affine_inv, n_samples);

    const int total_threads = NPIX * 32;  // one warp per pixel
    const int block = 256;
    const int grid  = (total_threads + block - 1) / block;
    drr_kernel<<<grid, block>>>(volume, out);
}